// round 14
// baseline (speedup 1.0000x reference)
#include <cuda_runtime.h>
#include <cuda_bf16.h>

// Fixed shapes: B=4, L=2048
#define BQ 4
#define LQ 2048
#define MSEG (LQ - 1)              // 2047 segments per path

#define THREADS 256
#define NSET 2                      // packed f32x2 sets per thread
#define UI (2 * NSET)               // 4 i-segments per thread
#define IPB (THREADS * UI)          // 1024
#define IT 2                        // ceil(2047/1024)
#define JT 54
#define JPB 38                      // 54*38 = 2052 >= 2047
#define NBLOCKS (BQ * IT * JT)      // 432 <= 148 SMs * 3 CTAs
#define PER_B (IT * JT)             // 108 partials per batch

typedef unsigned long long u64;

// Scratch (no cudaMalloc allowed)
__device__ float        g_partial[NBLOCKS];
__device__ unsigned int g_count = 0;

// ---- packed f32x2 helpers (sm_100+ PTX) ----
__device__ __forceinline__ u64 pk2(float lo, float hi) {
    u64 r; asm("mov.b64 %0, {%1, %2};" : "=l"(r) : "f"(lo), "f"(hi)); return r;
}
__device__ __forceinline__ void upk2(u64 v, float& lo, float& hi) {
    asm("mov.b64 {%0, %1}, %2;" : "=f"(lo), "=f"(hi) : "l"(v));
}
__device__ __forceinline__ u64 f2fma(u64 a, u64 b, u64 c) {
    u64 d; asm("fma.rn.f32x2 %0, %1, %2, %3;" : "=l"(d) : "l"(a), "l"(b), "l"(c)); return d;
}
__device__ __forceinline__ u64 f2add(u64 a, u64 b) {
    u64 d; asm("add.rn.f32x2 %0, %1, %2;" : "=l"(d) : "l"(a), "l"(b)); return d;
}
__device__ __forceinline__ u64 f2mul(u64 a, u64 b) {
    u64 d; asm("mul.rn.f32x2 %0, %1, %2;" : "=l"(d) : "l"(a), "l"(b)); return d;
}
__device__ __forceinline__ float frsq(float x) {
    float r; asm("rsqrt.approx.f32 %0, %1;" : "=f"(r) : "f"(x)); return r;
}

// q / (|q|+1e-12) ~= q * rsqrt(|q|^2)  (1e-12 relative; |q| ~ O(1))
__device__ __forceinline__ float3 norm_imag4(float4 q) {
    float s   = q.x * q.x + q.y * q.y + q.z * q.z + q.w * q.w;
    float inv = frsq(fmaxf(s, 1e-30f));
    return make_float3(q.y * inv, q.z * inv, q.w * inv);
}

__global__ __launch_bounds__(THREADS, 3)
void gauss_linking_fused(const float* __restrict__ qa,
                         const float* __restrict__ qb,
                         float* __restrict__ out) {
    __shared__ float  pA[(IPB + 1) * 3];                 // 12.3 KB
    __shared__ float  pB[(JPB + 1) * 3];
    // per-j packed duplicated operands + one zeroed guard row for prefetch
    __shared__ __align__(16) u64 sj[(JPB + 1) * 10];     // 3.1 KB
    __shared__ float  rwarp[THREADS / 32];
    __shared__ double sdd[BQ];
    __shared__ int    lastFlag;

    const int b  = blockIdx.z;
    const int it = blockIdx.y;
    const int jt = blockIdx.x;
    const int t  = threadIdx.x;

    // ---- Stage & normalize A-point tile ----
    const int i0     = it * IPB;
    const int segcnt = min(IPB, MSEG - i0);              // 1024 or 1023
    for (int p = t; p < segcnt + 1; p += THREADS) {
        float4 q = *reinterpret_cast<const float4*>(qa + ((long)(b * LQ + i0 + p)) * 4);
        float3 v = norm_imag4(q);
        pA[p * 3 + 0] = v.x; pA[p * 3 + 1] = v.y; pA[p * 3 + 2] = v.z;
    }

    // ---- Stage & normalize B-point tile, build duplicated per-j data ----
    const int j0     = jt * JPB;
    const int jcount = min(JPB, MSEG - j0);              // 38 (33 for last tile)
    if (t <= jcount) {
        float4 q = *reinterpret_cast<const float4*>(qb + ((long)(b * LQ + j0 + t)) * 4);
        float3 v = norm_imag4(q);
        pB[t * 3 + 0] = v.x; pB[t * 3 + 1] = v.y; pB[t * 3 + 2] = v.z;
    }
    __syncthreads();
    if (t < jcount) {
        float x0 = pB[t * 3 + 0], y0 = pB[t * 3 + 1], z0 = pB[t * 3 + 2];
        float x1 = pB[t * 3 + 3], y1 = pB[t * 3 + 4], z1 = pB[t * 3 + 5];
        float rbx = (x1 + x0) * 0.5f, rby = (y1 + y0) * 0.5f, rbz = (z1 + z0) * 0.5f;
        float dbx = x1 - x0,          dby = y1 - y0,          dbz = z1 - z0;
        float gx = rby * dbz - rbz * dby;                 // g = rb x db
        float gy = rbz * dbx - rbx * dbz;
        float gz = rbx * dby - rby * dbx;
        u64* s = sj + t * 10;
        s[0] = pk2(-rbx, -rbx);  s[1] = pk2(-rby, -rby);  s[2] = pk2(-rbz, -rbz);
        s[3] = pk2(dbx, dbx);    s[4] = pk2(dby, dby);    s[5] = pk2(dbz, dbz);
        s[6] = pk2(gx, gx);      s[7] = pk2(gy, gy);      s[8] = pk2(gz, gz);
    } else if (t == jcount) {
        // zero guard row so the software-pipeline prefetch of row jcount is safe
        u64* s = sj + t * 10;
        #pragma unroll
        for (int k = 0; k < 9; k++) s[k] = 0ull;
    }
    __syncthreads();

    // ---- Register-resident i-segments, packed: set s holds (u=2s lo, u=2s+1 hi) ----
    u64 axp[NSET], ayp[NSET], azp[NSET];
    u64 daxp[NSET], dayp[NSET], dazp[NSET];
    u64 haxp[NSET], hayp[NSET], hazp[NSET];
    #pragma unroll
    for (int s = 0; s < NSET; s++) {
        float ax[2], ay[2], az[2], dx[2], dy[2], dz[2], hx[2], hy[2], hz[2];
        #pragma unroll
        for (int h = 0; h < 2; h++) {
            int i = (2 * s + h) * THREADS + t;
            if (i < segcnt) {
                float x0 = pA[i * 3 + 0], y0 = pA[i * 3 + 1], z0 = pA[i * 3 + 2];
                float x1 = pA[i * 3 + 3], y1 = pA[i * 3 + 4], z1 = pA[i * 3 + 5];
                ax[h] = (x1 + x0) * 0.5f; ay[h] = (y1 + y0) * 0.5f; az[h] = (z1 + z0) * 0.5f;
                dx[h] = x1 - x0;          dy[h] = y1 - y0;          dz[h] = z1 - z0;
                hx[h] = ay[h] * dz[h] - az[h] * dy[h];    // ha = ra x da
                hy[h] = az[h] * dx[h] - ax[h] * dz[h];
                hz[h] = ax[h] * dy[h] - ay[h] * dx[h];
            } else {
                ax[h] = ay[h] = az[h] = 0.f;
                dx[h] = dy[h] = dz[h] = 0.f;
                hx[h] = hy[h] = hz[h] = 0.f;              // num = 0 -> contributes 0
            }
        }
        axp[s]  = pk2(ax[0], ax[1]);  ayp[s]  = pk2(ay[0], ay[1]);  azp[s]  = pk2(az[0], az[1]);
        daxp[s] = pk2(dx[0], dx[1]);  dayp[s] = pk2(dy[0], dy[1]);  dazp[s] = pk2(dz[0], dz[1]);
        haxp[s] = pk2(hx[0], hx[1]);  hayp[s] = pk2(hy[0], hy[1]);  hazp[s] = pk2(hz[0], hz[1]);
    }
    const u64 NEG3EPS = pk2(-3e-6f, -3e-6f);
    const u64 ONE2    = pk2(1.0f, 1.0f);
    const u64 TINY2   = pk2(1e-24f, 1e-24f);

    // ---- Main loop: software-pipelined (prefetch j+1 while computing j) ----
    // num = rd.(da x db) = (ra x da).db + da.(rb x db) = ha.db + da.g
    // 1/(|r|+eps)^3 = rs^3 * (1+eps*rs)^-3 ~= rs^3 * (1 - 3*eps*rs)
    u64 acc2[NSET] = {0ull, 0ull};
    ulonglong2 p01 = *reinterpret_cast<const ulonglong2*>(sj);      // -rbx -rby
    ulonglong2 p23 = *reinterpret_cast<const ulonglong2*>(sj + 2);  // -rbz  dbx
    ulonglong2 p45 = *reinterpret_cast<const ulonglong2*>(sj + 4);  //  dby  dbz
    ulonglong2 p67 = *reinterpret_cast<const ulonglong2*>(sj + 6);  //  gx   gy
    u64        gz2 = sj[8];

    #pragma unroll 1
    for (int j = 0; j < jcount; j++) {
        // Prefetch next j's operands (guard row makes j+1 == jcount safe)
        const u64* spn = sj + (j + 1) * 10;
        ulonglong2 n01 = *reinterpret_cast<const ulonglong2*>(spn);
        ulonglong2 n23 = *reinterpret_cast<const ulonglong2*>(spn + 2);
        ulonglong2 n45 = *reinterpret_cast<const ulonglong2*>(spn + 4);
        ulonglong2 n67 = *reinterpret_cast<const ulonglong2*>(spn + 6);
        u64        ngz = spn[8];

        // Phase 1: d2 (independent chains per set)
        u64 d2[NSET];
        #pragma unroll
        for (int s = 0; s < NSET; s++) {
            u64 rdx = f2add(axp[s], p01.x);
            u64 rdy = f2add(ayp[s], p01.y);
            u64 rdz = f2add(azp[s], p23.x);
            u64 d   = f2fma(rdx, rdx, TINY2);       // seed keeps d2 > 0 (no fmax)
            d       = f2fma(rdy, rdy, d);
            d2[s]   = f2fma(rdz, rdz, d);
        }
        // Phase 2: issue all MUFUs
        u64 rs[NSET];
        #pragma unroll
        for (int s = 0; s < NSET; s++) {
            float d0, d1;
            upk2(d2[s], d0, d1);
            rs[s] = pk2(frsq(d0), frsq(d1));
        }
        // Phase 3: numerators (independent of MUFU -> hides its latency)
        u64 num[NSET];
        #pragma unroll
        for (int s = 0; s < NSET; s++) {
            u64 n = f2fma(hazp[s], p45.y, f2fma(hayp[s], p45.x, f2mul(haxp[s], p23.y)));
            num[s] = f2fma(dazp[s], gz2, f2fma(dayp[s], p67.y, f2fma(daxp[s], p67.x, n)));
        }
        // Phase 4: epilogue
        #pragma unroll
        for (int s = 0; s < NSET; s++) {
            u64 rs3 = f2mul(f2mul(rs[s], rs[s]), rs[s]);
            u64 fac = f2fma(rs[s], NEG3EPS, ONE2);
            acc2[s] = f2fma(f2mul(num[s], rs3), fac, acc2[s]);
        }
        // Rotate pipeline registers
        p01 = n01; p23 = n23; p45 = n45; p67 = n67; gz2 = ngz;
    }

    float l0, h0, l1, h1;
    upk2(acc2[0], l0, h0);
    upk2(acc2[1], l1, h1);
    float acc = (l0 + h0) + (l1 + h1);

    // ---- Deterministic reduction: warp shuffle + single barrier ----
    #pragma unroll
    for (int off = 16; off >= 1; off >>= 1)
        acc += __shfl_down_sync(0xffffffffu, acc, off);
    if ((t & 31) == 0) rwarp[t >> 5] = acc;
    __syncthreads();

    if (t == 0) {
        float r = 0.0f;
        #pragma unroll
        for (int w = 0; w < THREADS / 32; w++) r += rwarp[w];
        g_partial[b * PER_B + it * JT + jt] = r;
        __threadfence();
        unsigned int tk = atomicAdd(&g_count, 1u);
        lastFlag = (tk == NBLOCKS - 1u) ? 1 : 0;
    }
    __syncthreads();

    // ---- Last-block-done final reduction (deterministic fixed order) ----
    if (lastFlag) {
        int w = t >> 5, l = t & 31;
        if (w < BQ) {
            double s = 0.0;
            for (int k = l; k < PER_B; k += 32)
                s += (double)__ldcg(&g_partial[w * PER_B + k]);
            #pragma unroll
            for (int off = 16; off >= 1; off >>= 1)
                s += __shfl_down_sync(0xffffffffu, s, off);
            if (l == 0) sdd[w] = fabs(s);
        }
        __syncthreads();
        if (t == 0) {
            double tot = sdd[0] + sdd[1] + sdd[2] + sdd[3];
            out[0] = (float)(tot / ((double)BQ * 4.0 * 3.14159265358979323846));
            g_count = 0;   // reset for next graph replay
        }
    }
}

extern "C" void kernel_launch(void* const* d_in, const int* in_sizes, int n_in,
                              void* d_out, int out_size) {
    const float* qa = (const float*)d_in[0];   // genomic_quats [B,L,4]
    const float* qb = (const float*)d_in[1];   // code_quats    [B,L,4]
    float* out = (float*)d_out;

    dim3 grid(JT, IT, BQ);                     // 432 blocks
    gauss_linking_fused<<<grid, THREADS>>>(qa, qb, out);
}